// round 2
// baseline (speedup 1.0000x reference)
#include <cuda_runtime.h>
#include <cuda_bf16.h>
#include <math.h>
#include <float.h>

// ---------------------------------------------------------------------------
// SampledSoftmax: probs = softmax(x @ W + b) over UNITS; loss = sampled
// softmax loss where sampled/true logits are GATHERED from the full logits.
//
// Pipeline (all on default stream, graph-capturable, allocation-free):
//   1. sgemm_bias:   logits = x @ W + b            -> d_out[0 .. N*U)
//   2. prep:         per-sample / per-target log(expected_count) adjustments
//   3. zero_loss:    d_out[out_size-1] = 0
//   4. loss_kernel:  per-row online logsumexp over {true, 8192 sampled}
//                    (gathered from raw logits), atomicAdd mean into loss slot
//   5. row_stats:    per-row max & inv-sum(exp)
//   6. normalize:    d_out[row,col] = exp(l - max) * inv_sum
// ---------------------------------------------------------------------------

#define BM 128
#define BN 128
#define BK 16
#define TM 8
#define TN 8
// 256 threads: 16x16 thread grid, each owns an 8x8 accumulator tile.

__device__ float g_row_max[8192];
__device__ float g_row_inv_sum[8192];
__device__ float g_true_adj[8192];
__device__ float g_samp_adj[16384];

// ---------------------------------------------------------------------------
// 1. SGEMM + bias.  A: [N,K] row-major, B: [K,U] row-major, C: [N,U].
//    U = 50257 (odd) => B/C rows are NOT 16B aligned: scalar B loads / C stores.
// ---------------------------------------------------------------------------
__global__ void __launch_bounds__(256, 2)
sgemm_bias_kernel(const float* __restrict__ A,
                  const float* __restrict__ B,
                  const float* __restrict__ bias,
                  float* __restrict__ C,
                  int Nrows, int K, int U)
{
    __shared__ float As[BK][BM];      // transposed A tile
    __shared__ float Bs[BK][BN];

    const int block_row = blockIdx.y * BM;
    const int block_col = blockIdx.x * BN;
    const int tid = threadIdx.x;
    const int tr = tid >> 4;          // 0..15
    const int tc = tid & 15;          // 0..15

    float acc[TM][TN];
#pragma unroll
    for (int i = 0; i < TM; i++)
#pragma unroll
        for (int j = 0; j < TN; j++) acc[i][j] = 0.f;

    float a_frag[TM], b_frag[TN];

    for (int k0 = 0; k0 < K; k0 += BK) {
        // Load A tile (128x16) as float4 (K=2048, always aligned), store transposed.
#pragma unroll
        for (int i = 0; i < 2; i++) {
            int idx = tid + i * 256;          // 0..511
            int m   = idx >> 2;               // 0..127
            int kq  = (idx & 3) << 2;         // 0,4,8,12
            float4 v = *(const float4*)&A[(size_t)(block_row + m) * K + k0 + kq];
            As[kq + 0][m] = v.x;
            As[kq + 1][m] = v.y;
            As[kq + 2][m] = v.z;
            As[kq + 3][m] = v.w;
        }
        // Load B tile (16x128), scalar (U odd -> unaligned for vec loads).
#pragma unroll
        for (int i = 0; i < 8; i++) {
            int idx = tid + i * 256;          // 0..2047
            int kk  = idx >> 7;               // 0..15
            int nn  = idx & 127;              // 0..127
            int col = block_col + nn;
            Bs[kk][nn] = (col < U) ? B[(size_t)(k0 + kk) * U + col] : 0.f;
        }
        __syncthreads();

#pragma unroll
        for (int kk = 0; kk < BK; kk++) {
#pragma unroll
            for (int i = 0; i < TM; i++) a_frag[i] = As[kk][tr * TM + i];
#pragma unroll
            for (int j = 0; j < TN; j++) b_frag[j] = Bs[kk][tc * TN + j];
#pragma unroll
            for (int i = 0; i < TM; i++)
#pragma unroll
                for (int j = 0; j < TN; j++)
                    acc[i][j] = fmaf(a_frag[i], b_frag[j], acc[i][j]);
        }
        __syncthreads();
    }

    // Epilogue: add bias, scalar stores (U odd).
#pragma unroll
    for (int i = 0; i < TM; i++) {
        int row = block_row + tr * TM + i;
        if (row >= Nrows) continue;
        float* crow = C + (size_t)row * U;
#pragma unroll
        for (int j = 0; j < TN; j++) {
            int col = block_col + tc * TN + j;
            if (col < U) crow[col] = acc[i][j] + bias[col];
        }
    }
}

// ---------------------------------------------------------------------------
// 2. Per-id log(expected_count) adjustments.
//    Replicates reference float32 math exactly: p = (log(f+2)-log(f+1))/logR,
//    ec = -expm1(NEG*log1p(-p)), adj = log(ec).
// ---------------------------------------------------------------------------
__device__ __forceinline__ float log_adjust(int id, float negf, float inv_log_range)
{
    float f  = (float)id;
    float pr = (logf(f + 2.0f) - logf(f + 1.0f)) * inv_log_range;
    float ec = -expm1f(negf * log1pf(-pr));
    return logf(ec);
}

__global__ void prep_kernel(const int* __restrict__ targets,
                            const int* __restrict__ sampled,
                            int Nrows, int NEGv, float negf, float inv_log_range)
{
    int i = blockIdx.x * blockDim.x + threadIdx.x;
    if (i < Nrows) g_true_adj[i] = log_adjust(targets[i], negf, inv_log_range);
    if (i < NEGv)  g_samp_adj[i] = log_adjust(sampled[i], negf, inv_log_range);
}

__global__ void zero_loss_kernel(float* loss) { *loss = 0.f; }

// ---------------------------------------------------------------------------
// 4. Loss: one block per row. Online logsumexp over true logit + sampled
//    logits gathered from the RAW logits (before softmax normalization).
//    Accidental hits (sampled id == target) are skipped (== masking to -1e20).
// ---------------------------------------------------------------------------
__global__ void loss_kernel(const float* __restrict__ logits,
                            const int* __restrict__ targets,
                            const int* __restrict__ sampled,
                            float* __restrict__ loss_out,
                            int U, int NEGv, int Nrows)
{
    const int row = blockIdx.x;
    const int tid = threadIdx.x;
    const float* p = logits + (size_t)row * U;
    const int t = targets[row];
    const float tl = p[t] - g_true_adj[row];

    float m = (tid == 0) ? tl : -FLT_MAX;
    float s = (tid == 0) ? 1.0f : 0.0f;

    for (int j = tid; j < NEGv; j += 256) {
        int id = sampled[j];
        if (id == t) continue;                    // accidental-hit mask
        float v = p[id] - g_samp_adj[j];
        if (v > m) { s = s * __expf(m - v) + 1.0f; m = v; }
        else       { s += __expf(v - m); }
    }

    __shared__ float smM[256], smS[256];
    smM[tid] = m; smS[tid] = s;
    __syncthreads();
    for (int str = 128; str > 0; str >>= 1) {
        if (tid < str) {
            float m1 = smM[tid], s1 = smS[tid];
            float m2 = smM[tid + str], s2 = smS[tid + str];
            float M = fmaxf(m1, m2);
            smS[tid] = s1 * __expf(m1 - M) + s2 * __expf(m2 - M);
            smM[tid] = M;
        }
        __syncthreads();
    }
    if (tid == 0) {
        float per_ex = smM[0] + logf(smS[0]) - tl;
        atomicAdd(loss_out, per_ex / (float)Nrows);
    }
}

// ---------------------------------------------------------------------------
// 5. Row stats: max + inverse sum(exp) per row.
// ---------------------------------------------------------------------------
__global__ void row_stats_kernel(const float* __restrict__ logits, int U)
{
    const int row = blockIdx.x;
    const int tid = threadIdx.x;
    const float* p = logits + (size_t)row * U;

    __shared__ float sm[256];

    float m = -FLT_MAX;
    for (int i = tid; i < U; i += 256) m = fmaxf(m, p[i]);
    sm[tid] = m;
    __syncthreads();
    for (int s = 128; s > 0; s >>= 1) {
        if (tid < s) sm[tid] = fmaxf(sm[tid], sm[tid + s]);
        __syncthreads();
    }
    const float rmax = sm[0];
    __syncthreads();

    float sum = 0.f;
    for (int i = tid; i < U; i += 256) sum += __expf(p[i] - rmax);
    sm[tid] = sum;
    __syncthreads();
    for (int s = 128; s > 0; s >>= 1) {
        if (tid < s) sm[tid] += sm[tid + s];
        __syncthreads();
    }
    if (tid == 0) {
        g_row_max[row] = rmax;
        g_row_inv_sum[row] = 1.0f / sm[0];
    }
}

// ---------------------------------------------------------------------------
// 6. Normalize in place: logits -> probs.
// ---------------------------------------------------------------------------
__global__ void normalize_kernel(float* __restrict__ logits, int U)
{
    const int row = blockIdx.y;
    const float rmax = g_row_max[row];
    const float rinv = g_row_inv_sum[row];
    float* p = logits + (size_t)row * U;

    int base = blockIdx.x * 2048;
    for (int i = base + threadIdx.x; i < base + 2048 && i < U; i += 256) {
        p[i] = __expf(p[i] - rmax) * rinv;
    }
}

// ---------------------------------------------------------------------------
extern "C" void kernel_launch(void* const* d_in, const int* in_sizes, int n_in,
                              void* d_out, int out_size)
{
    const float* pred    = (const float*)d_in[0];   // [B,S,C]
    const int*   targets = (const int*)  d_in[1];   // [B,S]
    const float* weight  = (const float*)d_in[2];   // [C,UNITS]
    const float* bias    = (const float*)d_in[3];   // [UNITS]
    const int*   sampled = (const int*)  d_in[4];   // [NEG]

    const int N    = in_sizes[1];                   // B*S = 2048
    const int U    = in_sizes[3];                   // 50257
    const int C    = in_sizes[2] / U;               // 2048
    const int NEGv = in_sizes[4];                   // 8192

    float* probs = (float*)d_out;                   // [N, U]
    float* loss  = (float*)d_out + (out_size - 1);  // scalar at the end

    const float inv_log_range = 1.0f / logf((float)U + 1.0f);

    // 1. logits = x @ W + b  (written into probs buffer)
    dim3 ggrid((U + BN - 1) / BN, (N + BM - 1) / BM);
    sgemm_bias_kernel<<<ggrid, 256>>>(pred, weight, bias, probs, N, C, U);

    // 2. adjustment tables
    int prep_n = (N > NEGv ? N : NEGv);
    prep_kernel<<<(prep_n + 255) / 256, 256>>>(targets, sampled, N, NEGv,
                                               (float)NEGv, inv_log_range);

    // 3-4. loss from RAW logits (before normalization)
    zero_loss_kernel<<<1, 1>>>(loss);
    loss_kernel<<<N, 256>>>(probs, targets, sampled, loss, U, NEGv, N);

    // 5-6. softmax normalization in place
    row_stats_kernel<<<N, 256>>>(probs, U);
    dim3 ngrid((U + 2047) / 2048, N);
    normalize_kernel<<<ngrid, 256>>>(probs, U);
}

// round 4
// speedup vs baseline: 2.3357x; 2.3357x over previous
#include <cuda_runtime.h>
#include <cuda_bf16.h>
#include <math.h>
#include <float.h>
#include <stdint.h>

// ---------------------------------------------------------------------------
// SampledSoftmax on GB300. NOTE: harness ptxas targets BASE sm_103 (no 'a'
// features), so tcgen05/TMEM are unavailable. Tensor path = mma.sync bf16
// (HMMA), with error-compensated bf16x3 split for fp32-grade accuracy:
//   C = Ah*Bh + Ah*Bl + Al*Bh   (fp32 accumulate)
//
// Pipeline:
//   0a. convA: predictions fp32 -> A_hi/A_lo bf16 [N,C]
//   0b. convB: kernel fp32 [C,U] -> transposed B_hi/B_lo bf16 [Upad,C]
//   1.  gemm_bf16x3: mma.sync GEMM (+bias) -> logits in d_out
//   2.  prep + loss: sampled-softmax loss from gathered raw logits
//   3.  row_stats + normalize: softmax in place
// ---------------------------------------------------------------------------

#define NROWS  2048
#define KDIM   2048
#define UPAD   50432          // U rounded up to 128
#define NEGMAX 16384

__device__ __align__(16) __nv_bfloat16 g_Ah[(size_t)NROWS * KDIM];
__device__ __align__(16) __nv_bfloat16 g_Al[(size_t)NROWS * KDIM];
__device__ __align__(16) __nv_bfloat16 g_Bh[(size_t)UPAD * KDIM];
__device__ __align__(16) __nv_bfloat16 g_Bl[(size_t)UPAD * KDIM];

__device__ float g_row_max[8192];
__device__ float g_row_inv_sum[8192];
__device__ float g_true_adj[8192];
__device__ float g_samp_adj[NEGMAX];

// ---------------- PTX helpers (base sm_103-safe: sm_80+ features only) -----
__device__ __forceinline__ uint32_t smem_to_u32(const void* p) {
    uint32_t a;
    asm("{ .reg .u64 t; cvta.to.shared.u64 t, %1; cvt.u32.u64 %0, t; }"
        : "=r"(a) : "l"(p));
    return a;
}
__device__ __forceinline__ void cp_async16(uint32_t dst, const void* src) {
    asm volatile("cp.async.cg.shared.global [%0], [%1], 16;"
        :: "r"(dst), "l"(__cvta_generic_to_global(src)));
}
#define CP_ASYNC_COMMIT() asm volatile("cp.async.commit_group;" ::: "memory")
#define CP_ASYNC_WAIT(n)  asm volatile("cp.async.wait_group %0;" :: "n"(n) : "memory")

__device__ __forceinline__ void ldsm_x4(uint32_t addr, uint32_t* r) {
    asm volatile("ldmatrix.sync.aligned.m8n8.x4.shared.b16 {%0,%1,%2,%3}, [%4];"
        : "=r"(r[0]), "=r"(r[1]), "=r"(r[2]), "=r"(r[3]) : "r"(addr));
}
__device__ __forceinline__ void mma_bf16(float* c, const uint32_t* a,
                                         uint32_t b0, uint32_t b1) {
    asm volatile(
        "mma.sync.aligned.m16n8k16.row.col.f32.bf16.bf16.f32 "
        "{%0,%1,%2,%3}, {%4,%5,%6,%7}, {%8,%9}, {%0,%1,%2,%3};"
        : "+f"(c[0]), "+f"(c[1]), "+f"(c[2]), "+f"(c[3])
        : "r"(a[0]), "r"(a[1]), "r"(a[2]), "r"(a[3]), "r"(b0), "r"(b1));
}

// ---------------------------------------------------------------------------
// 0a. split A into hi/lo bf16
// ---------------------------------------------------------------------------
__global__ void convA_kernel(const float* __restrict__ A, int total)
{
    int i = blockIdx.x * blockDim.x + threadIdx.x;
    if (i >= total) return;
    float v = A[i];
    __nv_bfloat16 h = __float2bfloat16(v);
    __nv_bfloat16 l = __float2bfloat16(v - __bfloat162float(h));
    g_Ah[i] = h; g_Al[i] = l;
}

// ---------------------------------------------------------------------------
// 0b. split + transpose B: [K,U] fp32 -> [Upad,K] bf16 hi/lo (zeros n>=U)
// ---------------------------------------------------------------------------
__global__ void convB_kernel(const float* __restrict__ B, int K, int U)
{
    __shared__ float tile[32][33];
    int k0 = blockIdx.x * 32, n0 = blockIdx.y * 32;
    int tx = threadIdx.x, ty = threadIdx.y;     // 32 x 8
#pragma unroll
    for (int i = 0; i < 32; i += 8) {
        int k = k0 + ty + i, n = n0 + tx;
        tile[ty + i][tx] = (n < U) ? B[(size_t)k * U + n] : 0.f;
    }
    __syncthreads();
#pragma unroll
    for (int i = 0; i < 32; i += 8) {
        int n = n0 + ty + i, kk = k0 + tx;
        float v = tile[tx][ty + i];
        __nv_bfloat16 h = __float2bfloat16(v);
        __nv_bfloat16 l = __float2bfloat16(v - __bfloat162float(h));
        g_Bh[(size_t)n * K + kk] = h;
        g_Bl[(size_t)n * K + kk] = l;
    }
}

// ---------------------------------------------------------------------------
// 1. mma.sync bf16x3 GEMM. CTA tile 128x128, BK=32, double-buffered cp.async.
//    8 warps in 2(M) x 4(N); warp tile 64x32 -> 4x4 m16n8 frags.
//    SMEM stage: Ah/Al/Bh/Bl each [128][40] bf16 (40 = 32 + 8 pad, so ldmatrix
//    rows (80B stride) are bank-conflict-free). Stage = 40960 B, 2 stages.
// ---------------------------------------------------------------------------
#define GEMM_SMEM (2 * 40960)

__global__ void __launch_bounds__(256, 1)
gemm_bf16x3_kernel(const float* __restrict__ bias, float* __restrict__ C,
                   int K, int U)
{
    extern __shared__ char smem_raw[];
    const uint32_t sb = smem_to_u32(smem_raw);
    const int tid   = threadIdx.x;
    const int lane  = tid & 31;
    const int wid   = tid >> 5;
    const int warp_m = wid >> 2;          // 0..1
    const int warp_n = wid & 3;           // 0..3
    const int m0 = blockIdx.x * 128;
    const int n0 = blockIdx.y * 128;

    float acc[4][4][4];
#pragma unroll
    for (int i = 0; i < 4; i++)
#pragma unroll
        for (int j = 0; j < 4; j++)
#pragma unroll
            for (int e = 0; e < 4; e++) acc[i][j][e] = 0.f;

    // ldmatrix address bases (bytes within a stage)
    const int grp = lane >> 3, lr = lane & 7;
    const uint32_t a_base = (uint32_t)(warp_m * 64 + ((grp & 1) << 3) + lr) * 80
                          + ((grp >> 1) << 4);
    const uint32_t b_base = (uint32_t)(warp_n * 32 + ((grp >> 1) << 3) + lr) * 80
                          + ((grp & 1) << 4);

    const int NS = K / 32;

    // stage loader: 512 16B chunks per matrix, 4 matrices
    auto load_stage = [&](int s) {
        const uint32_t st = sb + (uint32_t)(s & 1) * 40960;
        const int k0 = s * 32;
#pragma unroll
        for (int c = tid; c < 512; c += 256) {
            int r = c >> 2, q = c & 3;
            uint32_t off = (uint32_t)(r * 80 + q * 16);
            const size_t gA = (size_t)(m0 + r) * K + k0 + q * 8;
            const size_t gB = (size_t)(n0 + r) * K + k0 + q * 8;
            cp_async16(st + off,         &g_Ah[gA]);
            cp_async16(st + 10240 + off, &g_Al[gA]);
            cp_async16(st + 20480 + off, &g_Bh[gB]);
            cp_async16(st + 30720 + off, &g_Bl[gB]);
        }
    };

    load_stage(0);
    CP_ASYNC_COMMIT();

    for (int s = 0; s < NS; s++) {
        if (s + 1 < NS) {
            load_stage(s + 1);
            CP_ASYNC_COMMIT();
            CP_ASYNC_WAIT(1);
        } else {
            CP_ASYNC_WAIT(0);
        }
        __syncthreads();

        const uint32_t st = sb + (uint32_t)(s & 1) * 40960;
#pragma unroll
        for (int kb = 0; kb < 2; kb++) {
            uint32_t ah[4][4], al[4][4], bh[2][4], bl[2][4];
#pragma unroll
            for (int mi = 0; mi < 4; mi++) {
                uint32_t ao = st + a_base + (uint32_t)(mi * 1280 + kb * 32);
                ldsm_x4(ao,         ah[mi]);
                ldsm_x4(ao + 10240, al[mi]);
            }
#pragma unroll
            for (int ng = 0; ng < 2; ng++) {
                uint32_t bo = st + 20480 + b_base + (uint32_t)(ng * 1280 + kb * 32);
                ldsm_x4(bo,         bh[ng]);
                ldsm_x4(bo + 10240, bl[ng]);
            }
#pragma unroll
            for (int mi = 0; mi < 4; mi++) {
#pragma unroll
                for (int nj = 0; nj < 4; nj++) {
                    const int ng = nj >> 1, pp = (nj & 1) * 2;
                    mma_bf16(acc[mi][nj], ah[mi], bh[ng][pp], bh[ng][pp + 1]);
                    mma_bf16(acc[mi][nj], ah[mi], bl[ng][pp], bl[ng][pp + 1]);
                    mma_bf16(acc[mi][nj], al[mi], bh[ng][pp], bh[ng][pp + 1]);
                }
            }
        }
        __syncthreads();
    }

    // epilogue: direct global stores with bias
    const int r_base = m0 + warp_m * 64 + (lane >> 2);
    const int c_base = n0 + warp_n * 32 + (lane & 3) * 2;
#pragma unroll
    for (int nj = 0; nj < 4; nj++) {
        const int col = c_base + nj * 8;
        const bool v0 = (col < U), v1 = (col + 1 < U);
        const float bz0 = v0 ? bias[col] : 0.f;
        const float bz1 = v1 ? bias[col + 1] : 0.f;
#pragma unroll
        for (int mi = 0; mi < 4; mi++) {
            const int row0 = r_base + mi * 16;
            const int row1 = row0 + 8;
            if (v0) {
                C[(size_t)row0 * U + col] = acc[mi][nj][0] + bz0;
                C[(size_t)row1 * U + col] = acc[mi][nj][2] + bz0;
            }
            if (v1) {
                C[(size_t)row0 * U + col + 1] = acc[mi][nj][1] + bz1;
                C[(size_t)row1 * U + col + 1] = acc[mi][nj][3] + bz1;
            }
        }
    }
}

// ---------------------------------------------------------------------------
// 2. log(expected_count) adjustments (matches reference fp32 math)
// ---------------------------------------------------------------------------
__device__ __forceinline__ float log_adjust(int id, float negf, float inv_log_range)
{
    float f  = (float)id;
    float pr = (logf(f + 2.0f) - logf(f + 1.0f)) * inv_log_range;
    float ec = -expm1f(negf * log1pf(-pr));
    return logf(ec);
}

__global__ void prep_kernel(const int* __restrict__ targets,
                            const int* __restrict__ sampled,
                            int Nr, int NEGv, float negf, float inv_log_range)
{
    int i = blockIdx.x * blockDim.x + threadIdx.x;
    if (i < Nr)   g_true_adj[i] = log_adjust(targets[i], negf, inv_log_range);
    if (i < NEGv) g_samp_adj[i] = log_adjust(sampled[i], negf, inv_log_range);
}

__global__ void zero_loss_kernel(float* loss) { *loss = 0.f; }

// ---------------------------------------------------------------------------
// 3. loss: per-row online logsumexp over gathered raw logits
// ---------------------------------------------------------------------------
__global__ void loss_kernel(const float* __restrict__ logits,
                            const int* __restrict__ targets,
                            const int* __restrict__ sampled,
                            float* __restrict__ loss_out,
                            int U, int NEGv, int Nr)
{
    const int row = blockIdx.x;
    const int tid = threadIdx.x;
    const float* p = logits + (size_t)row * U;
    const int t = targets[row];
    const float tl = p[t] - g_true_adj[row];

    float m = (tid == 0) ? tl : -FLT_MAX;
    float s = (tid == 0) ? 1.0f : 0.0f;

    for (int j = tid; j < NEGv; j += 256) {
        int id = sampled[j];
        if (id == t) continue;
        float v = p[id] - g_samp_adj[j];
        if (v > m) { s = s * __expf(m - v) + 1.0f; m = v; }
        else       { s += __expf(v - m); }
    }

    __shared__ float smM[256], smS[256];
    smM[tid] = m; smS[tid] = s;
    __syncthreads();
    for (int str = 128; str > 0; str >>= 1) {
        if (tid < str) {
            float m1 = smM[tid], s1 = smS[tid];
            float m2 = smM[tid + str], s2 = smS[tid + str];
            float M = fmaxf(m1, m2);
            smS[tid] = s1 * __expf(m1 - M) + s2 * __expf(m2 - M);
            smM[tid] = M;
        }
        __syncthreads();
    }
    if (tid == 0) {
        float per_ex = smM[0] + logf(smS[0]) - tl;
        atomicAdd(loss_out, per_ex / (float)Nr);
    }
}

// ---------------------------------------------------------------------------
// 4. softmax row stats + normalize
// ---------------------------------------------------------------------------
__global__ void row_stats_kernel(const float* __restrict__ logits, int U)
{
    const int row = blockIdx.x;
    const int tid = threadIdx.x;
    const float* p = logits + (size_t)row * U;
    __shared__ float sm[256];

    float m = -FLT_MAX;
    for (int i = tid; i < U; i += 256) m = fmaxf(m, p[i]);
    sm[tid] = m;
    __syncthreads();
    for (int s = 128; s > 0; s >>= 1) {
        if (tid < s) sm[tid] = fmaxf(sm[tid], sm[tid + s]);
        __syncthreads();
    }
    const float rmax = sm[0];
    __syncthreads();

    float sum = 0.f;
    for (int i = tid; i < U; i += 256) sum += __expf(p[i] - rmax);
    sm[tid] = sum;
    __syncthreads();
    for (int s = 128; s > 0; s >>= 1) {
        if (tid < s) sm[tid] += sm[tid + s];
        __syncthreads();
    }
    if (tid == 0) {
        g_row_max[row] = rmax;
        g_row_inv_sum[row] = 1.0f / sm[0];
    }
}

__global__ void normalize_kernel(float* __restrict__ logits, int U)
{
    const int row = blockIdx.y;
    const float rmax = g_row_max[row];
    const float rinv = g_row_inv_sum[row];
    float* p = logits + (size_t)row * U;
    int base = blockIdx.x * 2048;
    for (int i = base + threadIdx.x; i < base + 2048 && i < U; i += 256)
        p[i] = __expf(p[i] - rmax) * rinv;
}

// ---------------------------------------------------------------------------
extern "C" void kernel_launch(void* const* d_in, const int* in_sizes, int n_in,
                              void* d_out, int out_size)
{
    const float* pred    = (const float*)d_in[0];   // [B,S,C]
    const int*   targets = (const int*)  d_in[1];   // [B,S]
    const float* weight  = (const float*)d_in[2];   // [C,UNITS]
    const float* bias    = (const float*)d_in[3];   // [UNITS]
    const int*   sampled = (const int*)  d_in[4];   // [NEG]

    const int N    = in_sizes[1];                   // 2048
    const int U    = in_sizes[3];                   // 50257
    const int C    = in_sizes[2] / U;               // 2048
    const int NEGv = in_sizes[4];                   // 8192

    float* probs = (float*)d_out;
    float* loss  = (float*)d_out + (out_size - 1);

    const float inv_log_range = 1.0f / logf((float)U + 1.0f);
    const int Upad = ((U + 127) / 128) * 128;

    // 0. operand conversion / split
    convA_kernel<<<(N * C + 255) / 256, 256>>>(pred, N * C);
    convB_kernel<<<dim3(C / 32, ((U + 31) / 32)), dim3(32, 8)>>>(weight, C, U);

    // 1. GEMM -> logits (x fastest so m-tiles sharing a B column hit L2)
    static int smem_set = 0;
    if (!smem_set) {
        cudaFuncSetAttribute(gemm_bf16x3_kernel,
                             cudaFuncAttributeMaxDynamicSharedMemorySize, GEMM_SMEM);
        smem_set = 1;
    }
    dim3 ggrid(N / 128, Upad / 128);
    gemm_bf16x3_kernel<<<ggrid, 256, GEMM_SMEM>>>(bias, probs, C, U);

    // 2. adjustments + loss (raw logits)
    int prep_n = (N > NEGv ? N : NEGv);
    prep_kernel<<<(prep_n + 255) / 256, 256>>>(targets, sampled, N, NEGv,
                                               (float)NEGv, inv_log_range);
    zero_loss_kernel<<<1, 1>>>(loss);
    loss_kernel<<<N, 256>>>(probs, targets, sampled, loss, U, NEGv, N);

    // 3. softmax in place
    row_stats_kernel<<<N, 256>>>(probs, U);
    dim3 ngrid((U + 2047) / 2048, N);
    normalize_kernel<<<ngrid, 256>>>(probs, U);
}

// round 5
// speedup vs baseline: 2.6730x; 1.1444x over previous
#include <cuda_runtime.h>
#include <cuda_bf16.h>
#include <math.h>
#include <float.h>
#include <stdint.h>

// ---------------------------------------------------------------------------
// SampledSoftmax on GB300 (harness ptxas targets base sm_103: no tcgen05).
// Tensor path = mma.sync bf16 (HMMA) with error-compensated bf16x3 split:
//   C = Ah*Bh + Ah*Bl + Al*Bh  (fp32 accumulate)
// R4: CTA 128x256, warp tile 64x64, 3-stage cp.async pipeline, 1 sync/stage.
// ---------------------------------------------------------------------------

#define NROWS  2048
#define KDIM   2048
#define UPAD   50432          // U rounded up to 256
#define NEGMAX 16384

__device__ __align__(16) __nv_bfloat16 g_Ah[(size_t)NROWS * KDIM];
__device__ __align__(16) __nv_bfloat16 g_Al[(size_t)NROWS * KDIM];
__device__ __align__(16) __nv_bfloat16 g_Bh[(size_t)UPAD * KDIM];
__device__ __align__(16) __nv_bfloat16 g_Bl[(size_t)UPAD * KDIM];

__device__ float g_row_max[8192];
__device__ float g_row_inv_sum[8192];
__device__ float g_true_adj[8192];
__device__ float g_samp_adj[NEGMAX];

// ---------------- PTX helpers (sm_80+ only: base sm_103-safe) ----------------
__device__ __forceinline__ uint32_t smem_to_u32(const void* p) {
    uint32_t a;
    asm("{ .reg .u64 t; cvta.to.shared.u64 t, %1; cvt.u32.u64 %0, t; }"
        : "=r"(a) : "l"(p));
    return a;
}
__device__ __forceinline__ void cp_async16(uint32_t dst, const void* src) {
    asm volatile("cp.async.cg.shared.global [%0], [%1], 16;"
        :: "r"(dst), "l"(__cvta_generic_to_global(src)));
}
#define CP_ASYNC_COMMIT() asm volatile("cp.async.commit_group;" ::: "memory")
#define CP_ASYNC_WAIT(n)  asm volatile("cp.async.wait_group %0;" :: "n"(n) : "memory")

__device__ __forceinline__ void ldsm_x4(uint32_t addr, uint32_t* r) {
    asm volatile("ldmatrix.sync.aligned.m8n8.x4.shared.b16 {%0,%1,%2,%3}, [%4];"
        : "=r"(r[0]), "=r"(r[1]), "=r"(r[2]), "=r"(r[3]) : "r"(addr));
}
__device__ __forceinline__ void mma_bf16(float* c, const uint32_t* a,
                                         uint32_t b0, uint32_t b1) {
    asm volatile(
        "mma.sync.aligned.m16n8k16.row.col.f32.bf16.bf16.f32 "
        "{%0,%1,%2,%3}, {%4,%5,%6,%7}, {%8,%9}, {%0,%1,%2,%3};"
        : "+f"(c[0]), "+f"(c[1]), "+f"(c[2]), "+f"(c[3])
        : "r"(a[0]), "r"(a[1]), "r"(a[2]), "r"(a[3]), "r"(b0), "r"(b1));
}

// ---------------------------------------------------------------------------
// 0a. split A into hi/lo bf16
// ---------------------------------------------------------------------------
__global__ void convA_kernel(const float* __restrict__ A, int total)
{
    int i = blockIdx.x * blockDim.x + threadIdx.x;
    if (i >= total) return;
    float v = A[i];
    __nv_bfloat16 h = __float2bfloat16(v);
    __nv_bfloat16 l = __float2bfloat16(v - __bfloat162float(h));
    g_Ah[i] = h; g_Al[i] = l;
}

// ---------------------------------------------------------------------------
// 0b. split + transpose B: [K,U] fp32 -> [UPAD,K] bf16 hi/lo (zeros n>=U)
// ---------------------------------------------------------------------------
__global__ void convB_kernel(const float* __restrict__ B, int K, int U)
{
    __shared__ float tile[32][33];
    int k0 = blockIdx.x * 32, n0 = blockIdx.y * 32;
    int tx = threadIdx.x, ty = threadIdx.y;     // 32 x 8
#pragma unroll
    for (int i = 0; i < 32; i += 8) {
        int k = k0 + ty + i, n = n0 + tx;
        tile[ty + i][tx] = (n < U) ? B[(size_t)k * U + n] : 0.f;
    }
    __syncthreads();
#pragma unroll
    for (int i = 0; i < 32; i += 8) {
        int n = n0 + ty + i, kk = k0 + tx;
        float v = tile[tx][ty + i];
        __nv_bfloat16 h = __float2bfloat16(v);
        __nv_bfloat16 l = __float2bfloat16(v - __bfloat162float(h));
        g_Bh[(size_t)n * K + kk] = h;
        g_Bl[(size_t)n * K + kk] = l;
    }
}

// ---------------------------------------------------------------------------
// 1. mma.sync bf16x3 GEMM. CTA 128x256, BK=32, 3-stage cp.async pipeline.
//    8 warps in 2(M) x 4(N); warp tile 64x64 -> 4x8 m16n8 frags.
//    SMEM stage: Ah/Al [128][40]h, Bh/Bl [256][40]h (40 = 32+8 pad, 80B rows).
//    Stage = 61440 B, 3 stages = 184320 B.
// ---------------------------------------------------------------------------
#define ST_AH 0
#define ST_AL 10240
#define ST_BH 20480
#define ST_BL 40960
#define STAGE_BYTES 61440
#define NSTAGE 3
#define GEMM_SMEM (NSTAGE * STAGE_BYTES)

__global__ void __launch_bounds__(256, 1)
gemm_bf16x3_kernel(const float* __restrict__ bias, float* __restrict__ C,
                   int K, int U)
{
    extern __shared__ char smem_raw[];
    const uint32_t sb = smem_to_u32(smem_raw);
    const int tid    = threadIdx.x;
    const int lane   = tid & 31;
    const int wid    = tid >> 5;
    const int warp_m = wid >> 2;          // 0..1
    const int warp_n = wid & 3;           // 0..3
    const int m0 = blockIdx.x * 128;
    const int n0 = blockIdx.y * 256;

    float acc[4][8][4];
#pragma unroll
    for (int i = 0; i < 4; i++)
#pragma unroll
        for (int j = 0; j < 8; j++)
#pragma unroll
            for (int e = 0; e < 4; e++) acc[i][j][e] = 0.f;

    // ldmatrix lane address bases (bytes within a stage region)
    const int grp = lane >> 3, lr = lane & 7;
    const uint32_t a_base = (uint32_t)(warp_m * 64 + ((grp & 1) << 3) + lr) * 80
                          + ((grp >> 1) << 4);
    const uint32_t b_base = (uint32_t)(warp_n * 64 + ((grp >> 1) << 3) + lr) * 80
                          + ((grp & 1) << 4);

    const int NS = K / 32;

    auto load_stage = [&](int s) {
        const uint32_t st = sb + (uint32_t)(s % NSTAGE) * STAGE_BYTES;
        const int k0 = s * 32;
        // A: 128 rows x 4 16B-chunks (hi+lo)
#pragma unroll
        for (int c = tid; c < 512; c += 256) {
            int r = c >> 2, q = c & 3;
            uint32_t off = (uint32_t)(r * 80 + q * 16);
            const size_t gA = (size_t)(m0 + r) * K + k0 + q * 8;
            cp_async16(st + ST_AH + off, &g_Ah[gA]);
            cp_async16(st + ST_AL + off, &g_Al[gA]);
        }
        // B: 256 rows x 4 chunks (hi+lo)
#pragma unroll
        for (int c = tid; c < 1024; c += 256) {
            int r = c >> 2, q = c & 3;
            uint32_t off = (uint32_t)(r * 80 + q * 16);
            const size_t gB = (size_t)(n0 + r) * K + k0 + q * 8;
            cp_async16(st + ST_BH + off, &g_Bh[gB]);
            cp_async16(st + ST_BL + off, &g_Bl[gB]);
        }
    };

    load_stage(0); CP_ASYNC_COMMIT();
    load_stage(1); CP_ASYNC_COMMIT();

    for (int s = 0; s < NS; s++) {
        CP_ASYNC_WAIT(1);                 // stage s resident (s+1 may be in flight)
        __syncthreads();                  // also: all warps done with buf (s-1)%3
        if (s + 2 < NS) { load_stage(s + 2); CP_ASYNC_COMMIT(); }

        const uint32_t st = sb + (uint32_t)(s % NSTAGE) * STAGE_BYTES;
#pragma unroll
        for (int kb = 0; kb < 2; kb++) {
            uint32_t ah[4][4], al[4][4], bh[4][4], bl[4][4];
#pragma unroll
            for (int mi = 0; mi < 4; mi++) {
                uint32_t ao = st + a_base + (uint32_t)(mi * 1280 + kb * 32);
                ldsm_x4(ao + ST_AH, ah[mi]);
                ldsm_x4(ao + ST_AL, al[mi]);
            }
#pragma unroll
            for (int g = 0; g < 4; g++) {
                uint32_t bo = st + b_base + (uint32_t)(g * 1280 + kb * 32);
                ldsm_x4(bo + ST_BH, bh[g]);
                ldsm_x4(bo + ST_BL, bl[g]);
            }
#pragma unroll
            for (int mi = 0; mi < 4; mi++) {
#pragma unroll
                for (int nj = 0; nj < 8; nj++) {
                    const int g = nj >> 1, pp = (nj & 1) * 2;
                    mma_bf16(acc[mi][nj], ah[mi], bh[g][pp], bh[g][pp + 1]);
                    mma_bf16(acc[mi][nj], ah[mi], bl[g][pp], bl[g][pp + 1]);
                    mma_bf16(acc[mi][nj], al[mi], bh[g][pp], bh[g][pp + 1]);
                }
            }
        }
    }

    // epilogue: direct global stores with bias
    const int r_base = m0 + warp_m * 64 + (lane >> 2);
    const int c_base = n0 + warp_n * 64 + (lane & 3) * 2;
#pragma unroll
    for (int nj = 0; nj < 8; nj++) {
        const int col = c_base + nj * 8;
        const bool v0 = (col < U), v1 = (col + 1 < U);
        const float bz0 = v0 ? bias[col] : 0.f;
        const float bz1 = v1 ? bias[col + 1] : 0.f;
#pragma unroll
        for (int mi = 0; mi < 4; mi++) {
            const int row0 = r_base + mi * 16;
            const int row1 = row0 + 8;
            if (v0) {
                C[(size_t)row0 * U + col] = acc[mi][nj][0] + bz0;
                C[(size_t)row1 * U + col] = acc[mi][nj][2] + bz0;
            }
            if (v1) {
                C[(size_t)row0 * U + col + 1] = acc[mi][nj][1] + bz1;
                C[(size_t)row1 * U + col + 1] = acc[mi][nj][3] + bz1;
            }
        }
    }
}

// ---------------------------------------------------------------------------
// 2. log(expected_count) adjustments (matches reference fp32 math)
// ---------------------------------------------------------------------------
__device__ __forceinline__ float log_adjust(int id, float negf, float inv_log_range)
{
    float f  = (float)id;
    float pr = (logf(f + 2.0f) - logf(f + 1.0f)) * inv_log_range;
    float ec = -expm1f(negf * log1pf(-pr));
    return logf(ec);
}

__global__ void prep_kernel(const int* __restrict__ targets,
                            const int* __restrict__ sampled,
                            int Nr, int NEGv, float negf, float inv_log_range)
{
    int i = blockIdx.x * blockDim.x + threadIdx.x;
    if (i < Nr)   g_true_adj[i] = log_adjust(targets[i], negf, inv_log_range);
    if (i < NEGv) g_samp_adj[i] = log_adjust(sampled[i], negf, inv_log_range);
}

__global__ void zero_loss_kernel(float* loss) { *loss = 0.f; }

// ---------------------------------------------------------------------------
// 3. loss: per-row online logsumexp over gathered raw logits
// ---------------------------------------------------------------------------
__global__ void loss_kernel(const float* __restrict__ logits,
                            const int* __restrict__ targets,
                            const int* __restrict__ sampled,
                            float* __restrict__ loss_out,
                            int U, int NEGv, int Nr)
{
    const int row = blockIdx.x;
    const int tid = threadIdx.x;
    const float* p = logits + (size_t)row * U;
    const int t = targets[row];
    const float tl = p[t] - g_true_adj[row];

    float m = (tid == 0) ? tl : -FLT_MAX;
    float s = (tid == 0) ? 1.0f : 0.0f;

    for (int j = tid; j < NEGv; j += 256) {
        int id = sampled[j];
        if (id == t) continue;
        float v = p[id] - g_samp_adj[j];
        if (v > m) { s = s * __expf(m - v) + 1.0f; m = v; }
        else       { s += __expf(v - m); }
    }

    __shared__ float smM[256], smS[256];
    smM[tid] = m; smS[tid] = s;
    __syncthreads();
    for (int str = 128; str > 0; str >>= 1) {
        if (tid < str) {
            float m1 = smM[tid], s1 = smS[tid];
            float m2 = smM[tid + str], s2 = smS[tid + str];
            float M = fmaxf(m1, m2);
            smS[tid] = s1 * __expf(m1 - M) + s2 * __expf(m2 - M);
            smM[tid] = M;
        }
        __syncthreads();
    }
    if (tid == 0) {
        float per_ex = smM[0] + logf(smS[0]) - tl;
        atomicAdd(loss_out, per_ex / (float)Nr);
    }
}

// ---------------------------------------------------------------------------
// 4. softmax row stats + normalize
// ---------------------------------------------------------------------------
__global__ void row_stats_kernel(const float* __restrict__ logits, int U)
{
    const int row = blockIdx.x;
    const int tid = threadIdx.x;
    const float* p = logits + (size_t)row * U;
    __shared__ float sm[256];

    float m = -FLT_MAX;
    for (int i = tid; i < U; i += 256) m = fmaxf(m, p[i]);
    sm[tid] = m;
    __syncthreads();
    for (int s = 128; s > 0; s >>= 1) {
        if (tid < s) sm[tid] = fmaxf(sm[tid], sm[tid + s]);
        __syncthreads();
    }
    const float rmax = sm[0];
    __syncthreads();

    float sum = 0.f;
    for (int i = tid; i < U; i += 256) sum += __expf(p[i] - rmax);
    sm[tid] = sum;
    __syncthreads();
    for (int s = 128; s > 0; s >>= 1) {
        if (tid < s) sm[tid] += sm[tid + s];
        __syncthreads();
    }
    if (tid == 0) {
        g_row_max[row] = rmax;
        g_row_inv_sum[row] = 1.0f / sm[0];
    }
}

__global__ void normalize_kernel(float* __restrict__ logits, int U)
{
    const int row = blockIdx.y;
    const float rmax = g_row_max[row];
    const float rinv = g_row_inv_sum[row];
    float* p = logits + (size_t)row * U;
    int base = blockIdx.x * 2048;
    for (int i = base + threadIdx.x; i < base + 2048 && i < U; i += 256)
        p[i] = __expf(p[i] - rmax) * rinv;
}

// ---------------------------------------------------------------------------
extern "C" void kernel_launch(void* const* d_in, const int* in_sizes, int n_in,
                              void* d_out, int out_size)
{
    const float* pred    = (const float*)d_in[0];   // [B,S,C]
    const int*   targets = (const int*)  d_in[1];   // [B,S]
    const float* weight  = (const float*)d_in[2];   // [C,UNITS]
    const float* bias    = (const float*)d_in[3];   // [UNITS]
    const int*   sampled = (const int*)  d_in[4];   // [NEG]

    const int N    = in_sizes[1];                   // 2048
    const int U    = in_sizes[3];                   // 50257
    const int C    = in_sizes[2] / U;               // 2048
    const int NEGv = in_sizes[4];                   // 8192

    float* probs = (float*)d_out;
    float* loss  = (float*)d_out + (out_size - 1);

    const float inv_log_range = 1.0f / logf((float)U + 1.0f);

    // 0. operand conversion / split (cover full UPAD so padding rows are zero)
    convA_kernel<<<(N * C + 255) / 256, 256>>>(pred, N * C);
    convB_kernel<<<dim3(C / 32, UPAD / 32), dim3(32, 8)>>>(weight, C, U);

    // 1. GEMM -> logits (x fastest: m-tiles sharing a B column block hit L2)
    static int smem_set = 0;
    if (!smem_set) {
        cudaFuncSetAttribute(gemm_bf16x3_kernel,
                             cudaFuncAttributeMaxDynamicSharedMemorySize, GEMM_SMEM);
        smem_set = 1;
    }
    dim3 ggrid(N / 128, UPAD / 256);
    gemm_bf16x3_kernel<<<ggrid, 256, GEMM_SMEM>>>(bias, probs, C, U);

    // 2. adjustments + loss (raw logits)
    int prep_n = (N > NEGv ? N : NEGv);
    prep_kernel<<<(prep_n + 255) / 256, 256>>>(targets, sampled, N, NEGv,
                                               (float)NEGv, inv_log_range);
    zero_loss_kernel<<<1, 1>>>(loss);
    loss_kernel<<<N, 256>>>(probs, targets, sampled, loss, U, NEGv, N);

    // 3. softmax in place
    row_stats_kernel<<<N, 256>>>(probs, U);
    dim3 ngrid((U + 2047) / 2048, N);
    normalize_kernel<<<ngrid, 256>>>(probs, U);
}